// round 11
// baseline (speedup 1.0000x reference)
#include <cuda_runtime.h>
#include <cstdint>

// SpectralNetLoss: W [8192,8192] f32, Y [8192,32] f32 -> scalar f32.
// WY = W @ Y and d = W @ 1 in ONE tf32 GEMM (mma.sync m16n8k8, sm_80 baseline
// ISA — harness targets sm_103 without 'a'; tcgen05/TMA unavailable).
// B' = [Y^T ; ones] (40 x 8192) pre-fragmented per 32-k tile (LDS.128 reads).
// PERSISTENT: 296 CTAs (2/SM x 148) walk a flat rb-major stream of 16384
// (row-block, k-tile) tiles -> 1.2% load imbalance instead of 16%. Partial
// accumulators flushed with atomicAdd on rb boundaries (<= 2 flushes/CTA).

#define MDIM    8192
#define KDIM    32
#define NB      40                  // 32 Y cols + 8 ones cols (row sums d)
#define MT      128                 // rows per row-block
#define KT      32                  // K per tile
#define NRB     (MDIM / MT)         // 64 row-blocks
#define NKT     (MDIM / KT)         // 256 k-tiles per row-block
#define NTILES  (NRB * NKT)         // 16384 flat tiles
#define NCTAS   296                 // 2 per SM on 148 SMs
#define STAGES  4
#define THREADS 128

#define PITCH     36                         // W smem row pitch (bank-clean)
#define A_TILE_F  (MT * PITCH)               // 4608 floats
#define BFRAG_F   (NB * KT)                  // 1280 floats per k-tile
#define STAGE_F   (A_TILE_F + BFRAG_F)       // 5888 floats
#define STAGE_B   (STAGE_F * 4)              // 23552 B
#define DYN_SMEM  (STAGES * STAGE_B)         // 94208 B (2 CTAs/SM fits)

// Scratch (no device allocs allowed).
__device__ float g_B[NKT * BFRAG_F];          // fragmented B', 1.25 MB
__device__ float g_wy[MDIM * KDIM];           // final WY accumulator, 1 MB
__device__ float g_d[MDIM];                   // final row sums, 32 KB

__device__ __forceinline__ uint32_t smem_u32(const void* p) {
    return (uint32_t)__cvta_generic_to_shared(p);
}
__device__ __forceinline__ void cp_async16(uint32_t dst, const void* src) {
    asm volatile("cp.async.cg.shared.global [%0], [%1], 16;\n" :: "r"(dst), "l"(src));
}
#define CP_COMMIT() asm volatile("cp.async.commit_group;\n" ::: "memory")
#define CP_WAIT(n)  asm volatile("cp.async.wait_group %0;\n" :: "n"(n) : "memory")

__device__ __forceinline__ void mma_tf32(float* c, const uint32_t* a, uint32_t b0,
                                         uint32_t b1) {
    asm volatile(
        "mma.sync.aligned.m16n8k8.row.col.f32.tf32.tf32.f32 "
        "{%0,%1,%2,%3}, {%4,%5,%6,%7}, {%8,%9}, {%0,%1,%2,%3};"
        : "+f"(c[0]), "+f"(c[1]), "+f"(c[2]), "+f"(c[3])
        : "r"(a[0]), "r"(a[1]), "r"(a[2]), "r"(a[3]), "r"(b0), "r"(b1));
}

// ---------------------------------------------------------------------------
// Prep: build fragmented B' (coalesced), zero g_wy / g_d / out.
// Fragment flat index f -> (nt,ks2,g,tig,e):
//   f = (((nt*2+ks2)*8+g)*4+tig)*4+e,  n = nt*8+g,
//   k_local = (2*ks2 + (e>>1))*8 + tig + (e&1)*4,  value = (n<32)?Y[k][n]:1.
// ---------------------------------------------------------------------------
__global__ void __launch_bounds__(256)
prep_kernel(const float* __restrict__ Y, float* __restrict__ out) {
    __shared__ float Ys[KT][KDIM + 1];
    const int t   = blockIdx.x;          // k-tile 0..255
    const int tid = threadIdx.x;

    {   // coalesced 32x32 Y tile load
        const float4* src = (const float4*)(Y + (size_t)t * KT * KDIM);
        float4 v = src[tid];
        int j = tid >> 3, c = (tid & 7) * 4;
        Ys[j][c] = v.x; Ys[j][c + 1] = v.y; Ys[j][c + 2] = v.z; Ys[j][c + 3] = v.w;
    }
    __syncthreads();

    float* dst = g_B + (size_t)t * BFRAG_F;
    #pragma unroll
    for (int p = 0; p < BFRAG_F / 256; ++p) {
        int f   = tid + p * 256;
        int e   = f & 3;
        int tig = (f >> 2) & 3;
        int g   = (f >> 4) & 7;
        int ks2 = (f >> 7) & 1;
        int nt  = f >> 8;
        int n   = nt * 8 + g;
        int kl  = (2 * ks2 + (e >> 1)) * 8 + tig + (e & 1) * 4;
        dst[f] = (n < KDIM) ? Ys[kl][n] : 1.0f;
    }

    // zero accumulators: 256 blocks x 256 thr x 4 floats == 262144 == |g_wy|
    ((float4*)g_wy)[t * 256 + tid] = make_float4(0.f, 0.f, 0.f, 0.f);
    if (t < 32) g_d[t * 256 + tid] = 0.0f;
    if (t == 0 && tid == 0) out[0] = 0.0f;
}

// ---------------------------------------------------------------------------
// Main GEMM: persistent CTAs over flat (rb, kt) tile stream.
// ---------------------------------------------------------------------------
__global__ void __launch_bounds__(THREADS)
mma_main(const float* __restrict__ W) {
    extern __shared__ float sm[];

    const int tid  = threadIdx.x;
    const int wid  = tid >> 5;
    const int lid  = tid & 31;
    const int g    = lid >> 2;
    const int tig  = lid & 3;

    const int tS = (int)(((long long)blockIdx.x * NTILES) / NCTAS);
    const int tE = (int)(((long long)(blockIdx.x + 1) * NTILES) / NCTAS);

    const uint32_t sbase = smem_u32(sm);

    float acc[2][5][4];
    #pragma unroll
    for (int mh = 0; mh < 2; ++mh)
        #pragma unroll
        for (int nt = 0; nt < 5; ++nt)
            #pragma unroll
            for (int q = 0; q < 4; ++q) acc[mh][nt][q] = 0.0f;

    // ---- loader for flat tile ft: rb = ft>>8, kt = ft&255 ----
    auto load_tile = [&](int ft) {
        const uint32_t sb  = sbase + (ft & (STAGES - 1)) * STAGE_B;
        const int      rb  = ft >> 8;
        const int      ktl = ft & (NKT - 1);
        const float*   wsrc = W + (size_t)rb * MT * MDIM + ktl * KT;
        #pragma unroll
        for (int p = 0; p < 8; ++p) {                    // W: 1024 x 16B chunks
            int c = tid + p * 128;
            int r = c >> 3, ci = c & 7;
            cp_async16(sb + (r * PITCH + ci * 4) * 4,
                       wsrc + (size_t)r * MDIM + ci * 4);
        }
        const float* bsrc = g_B + (size_t)ktl * BFRAG_F;
        #pragma unroll
        for (int p = 0; p < 2; ++p) {
            int c = tid + p * 128;
            cp_async16(sb + A_TILE_F * 4 + c * 16, bsrc + c * 4);
        }
        if (tid < 64) {
            int c = 256 + tid;
            cp_async16(sb + A_TILE_F * 4 + c * 16, bsrc + c * 4);
        }
    };

    // ---- flush accumulators for row-block rb (atomicAdd), then zero ----
    auto flush = [&](int rb) {
        const int row0 = rb * MT;
        #pragma unroll
        for (int mh = 0; mh < 2; ++mh) {
            const int rA = row0 + wid * 32 + mh * 16 + g;
            const int rB = rA + 8;
            #pragma unroll
            for (int nt = 0; nt < 4; ++nt) {
                int col = nt * 8 + 2 * tig;
                atomicAdd(&g_wy[(size_t)rA * KDIM + col],     acc[mh][nt][0]);
                atomicAdd(&g_wy[(size_t)rA * KDIM + col + 1], acc[mh][nt][1]);
                atomicAdd(&g_wy[(size_t)rB * KDIM + col],     acc[mh][nt][2]);
                atomicAdd(&g_wy[(size_t)rB * KDIM + col + 1], acc[mh][nt][3]);
            }
            if (tig == 0) {
                atomicAdd(&g_d[rA], acc[mh][4][0]);
                atomicAdd(&g_d[rB], acc[mh][4][2]);
            }
            #pragma unroll
            for (int nt = 0; nt < 5; ++nt)
                #pragma unroll
                for (int q = 0; q < 4; ++q) acc[mh][nt][q] = 0.0f;
        }
    };

    // prologue
    #pragma unroll
    for (int t = tS; t < tS + STAGES - 1; ++t) {
        if (t < tE) load_tile(t);
        CP_COMMIT();
    }

    for (int t = tS; t < tE; ++t) {
        if (t + STAGES - 1 < tE) load_tile(t + STAGES - 1);
        CP_COMMIT();
        CP_WAIT(STAGES - 1);
        __syncthreads();

        const float* As = sm + (t & (STAGES - 1)) * STAGE_F + (wid * 32 + g) * PITCH;
        const float* Bs = sm + (t & (STAGES - 1)) * STAGE_F + A_TILE_F;

        #pragma unroll
        for (int ks2 = 0; ks2 < 2; ++ks2) {
            float4 b4[5];
            #pragma unroll
            for (int nt = 0; nt < 5; ++nt)
                b4[nt] = *(const float4*)&Bs[((nt * 2 + ks2) * 32 + lid) * 4];

            #pragma unroll
            for (int sub = 0; sub < 2; ++sub) {
                const int k0 = (ks2 * 2 + sub) * 8;
                uint32_t a0[4], a1[4];
                a0[0] = __float_as_uint(As[k0 + tig]);
                a0[1] = __float_as_uint(As[8 * PITCH + k0 + tig]);
                a0[2] = __float_as_uint(As[k0 + tig + 4]);
                a0[3] = __float_as_uint(As[8 * PITCH + k0 + tig + 4]);
                a1[0] = __float_as_uint(As[16 * PITCH + k0 + tig]);
                a1[1] = __float_as_uint(As[24 * PITCH + k0 + tig]);
                a1[2] = __float_as_uint(As[16 * PITCH + k0 + tig + 4]);
                a1[3] = __float_as_uint(As[24 * PITCH + k0 + tig + 4]);
                #pragma unroll
                for (int nt = 0; nt < 5; ++nt) {
                    uint32_t b0 = __float_as_uint(sub ? b4[nt].z : b4[nt].x);
                    uint32_t b1 = __float_as_uint(sub ? b4[nt].w : b4[nt].y);
                    mma_tf32(acc[0][nt], a0, b0, b1);
                    mma_tf32(acc[1][nt], a1, b0, b1);
                }
            }
        }
        __syncthreads();

        // end of row-block or end of run -> flush partial accumulators
        if (t + 1 == tE || ((t + 1) & (NKT - 1)) == 0) flush(t >> 8);
    }
}

// ---------------------------------------------------------------------------
// Loss: loss = sum Y*(Y - WY/d) / m. Warp per row.
// ---------------------------------------------------------------------------
__global__ void __launch_bounds__(256)
loss_kernel(const float* __restrict__ Y, float* __restrict__ out) {
    __shared__ float red[8];
    const int warp = threadIdx.x >> 5;
    const int lane = threadIdx.x & 31;
    const int row  = blockIdx.x * 8 + warp;

    float d  = g_d[row];
    float wy = g_wy[(size_t)row * KDIM + lane];
    float y  = Y[(size_t)row * KDIM + lane];
    float s  = y * (y - wy / d);

    #pragma unroll
    for (int o = 16; o; o >>= 1) s += __shfl_xor_sync(0xffffffffu, s, o);
    if (lane == 0) red[warp] = s;
    __syncthreads();
    if (threadIdx.x < 8) {
        s = red[threadIdx.x];
        #pragma unroll
        for (int o = 4; o; o >>= 1) s += __shfl_xor_sync(0xffu, s, o);
        if (threadIdx.x == 0) atomicAdd(out, s * (1.0f / (float)MDIM));
    }
}

// ---------------------------------------------------------------------------
extern "C" void kernel_launch(void* const* d_in, const int* in_sizes, int n_in,
                              void* d_out, int out_size) {
    const float* W = (const float*)d_in[0];
    const float* Y = (const float*)d_in[1];
    float* out = (float*)d_out;

    cudaFuncSetAttribute(mma_main, cudaFuncAttributeMaxDynamicSharedMemorySize,
                         DYN_SMEM);

    prep_kernel<<<NKT, 256>>>(Y, out);               // 256 blocks

    mma_main<<<NCTAS, THREADS, DYN_SMEM>>>(W);       // 296 persistent CTAs

    loss_kernel<<<MDIM / 8, 256>>>(Y, out);
}